// round 2
// baseline (speedup 1.0000x reference)
#include <cuda_runtime.h>
#include <cstdint>

// Problem constants
#define NROWS   16384      // B*T = 4*4096
#define N1      1024
#define N2      2048
#define TW1_STACK_FLOATS (10*512*4)     // 20480 floats per stack
#define TW2_FLOATS       (11*1024*4)    // 45056 floats
#define SMEM1_FLOATS (2*TW1_STACK_FLOATS + 2*1024)   // 2 stacks + 2 bias slices = 43008
#define SMEM2_FLOATS (TW2_FLOATS + 1024)             // 46080

// GLU intermediate scratch (B,T,2048) fp32 = 128MB, static device array (allocation-free)
__device__ float g_h[(size_t)NROWS * N2];

__device__ __forceinline__ float2 shfl_xor_f2(float2 v, int mask) {
    float2 r;
    r.x = __shfl_xor_sync(0xffffffffu, v.x, mask);
    r.y = __shfl_xor_sync(0xffffffffu, v.y, mask);
    return r;
}

// In-register butterfly over n = NREG*32 elements, 2 rows packed per float2.
// Element index e = r*32 + lane. Stages idx<5: partner differs in lane bits
// (shfl.xor); stages idx>=5: partner differs in reg index (local).
// Twiddle smem layout per stage: [pairs][2][2] contiguous, pairs = NREG*16.
template<int NREG, int NSTAGE>
__device__ __forceinline__ void bfly(float2 (&v)[NREG], const float* __restrict__ tws, int lane) {
    constexpr int TSTAGE = NREG * 64;   // floats per stage
    // ---- shuffle stages: stride 1,2,4,8,16 ----
    #pragma unroll
    for (int idx = 0; idx < 5; idx++) {
        const int s = 1 << idx;
        const float* tstage = tws + idx * TSTAGE;
        const int i = (lane >> idx) & 1;
        #pragma unroll
        for (int r = 0; r < NREG; r++) {
            const int e = r * 32 + lane;
            const int p = ((e >> (idx + 1)) << idx) | (e & (s - 1));
            float4 t = *(const float4*)(tstage + p * 4);
            float2 pv = shfl_xor_f2(v[r], s);
            float ta = i ? t.z : t.x;       // t[i][0]
            float tb = i ? t.w : t.y;       // t[i][1]
            float2 lo = i ? pv   : v[r];
            float2 hi = i ? v[r] : pv;
            v[r].x = ta * lo.x + tb * hi.x;
            v[r].y = ta * lo.y + tb * hi.y;
        }
    }
    // ---- register-local stages: stride 32 * (1<<(idx-5)) ----
    #pragma unroll
    for (int idx = 5; idx < NSTAGE; idx++) {
        const int rs = 1 << (idx - 5);
        const float* tstage = tws + idx * TSTAGE;
        #pragma unroll
        for (int r = 0; r < NREG; r++) {
            if (r & rs) continue;
            const int r2 = r | rs;
            const int e = r * 32 + lane;
            const int p = ((e >> (idx + 1)) << idx) | (e & ((1 << idx) - 1));
            float4 t = *(const float4*)(tstage + p * 4);
            float2 lo = v[r], hi = v[r2];
            v[r].x  = t.x * lo.x + t.y * hi.x;
            v[r].y  = t.x * lo.y + t.y * hi.y;
            v[r2].x = t.z * lo.x + t.w * hi.x;
            v[r2].y = t.z * lo.y + t.w * hi.y;
        }
    }
}

// Kernel 1: fc1 butterfly (4 stacks, n=1024) + bias + GLU -> g_h (rows x 2048).
// CTA handles stack-pair g = blockIdx.x & 1: stacks (g) [a] and (g+2) [gate],
// writing h[:, g*1024:(g+1)*1024]. Warp processes 2 rows at a time.
__global__ void __launch_bounds__(256, 1)
glu_k1(const float* __restrict__ x, const float* __restrict__ tw1,
       const float* __restrict__ b1) {
    extern __shared__ float sm[];
    const int pairg = blockIdx.x & 1;

    // Stage twiddles (stacks pairg and pairg+2) + bias slices into smem
    {
        const float4* s0 = (const float4*)(tw1 + pairg * TW1_STACK_FLOATS);
        const float4* s1 = (const float4*)(tw1 + (pairg + 2) * TW1_STACK_FLOATS);
        float4* d = (float4*)sm;
        for (int i = threadIdx.x; i < TW1_STACK_FLOATS / 4; i += 256) {
            d[i] = s0[i];
            d[TW1_STACK_FLOATS / 4 + i] = s1[i];
        }
        float* sb = sm + 2 * TW1_STACK_FLOATS;
        for (int i = threadIdx.x; i < 1024; i += 256) {
            sb[i]        = b1[pairg * 1024 + i];         // a-bias
            sb[1024 + i] = b1[(pairg + 2) * 1024 + i];   // gate-bias
        }
    }
    __syncthreads();

    const float* twsA = sm;                          // stack pairg
    const float* twsG = sm + TW1_STACK_FLOATS;       // stack pairg+2
    const float* sba  = sm + 2 * TW1_STACK_FLOATS;
    const float* sbg  = sba + 1024;

    const int lane = threadIdx.x & 31;
    const int warp = threadIdx.x >> 5;
    const int wglobal = (blockIdx.x >> 1) * 8 + warp;
    const int wstride = (gridDim.x >> 1) * 8;

    for (int rp = wglobal; rp < NROWS / 2; rp += wstride) {
        const float* xA = x + (size_t)(rp * 2) * N1;
        const float* xB = xA + N1;
        float2 v[32], gate[32];

        // gate stack first
        #pragma unroll
        for (int r = 0; r < 32; r++) { v[r].x = xA[r * 32 + lane]; v[r].y = xB[r * 32 + lane]; }
        bfly<32, 10>(v, twsG, lane);
        #pragma unroll
        for (int r = 0; r < 32; r++) {
            float bb = sbg[r * 32 + lane];
            gate[r].x = 1.0f / (1.0f + __expf(-(v[r].x + bb)));
            gate[r].y = 1.0f / (1.0f + __expf(-(v[r].y + bb)));
        }
        // a stack (x re-read; L2-resident)
        #pragma unroll
        for (int r = 0; r < 32; r++) { v[r].x = xA[r * 32 + lane]; v[r].y = xB[r * 32 + lane]; }
        bfly<32, 10>(v, twsA, lane);

        float* hA = g_h + (size_t)(rp * 2) * N2 + pairg * 1024;
        float* hB = hA + N2;
        #pragma unroll
        for (int r = 0; r < 32; r++) {
            float bb = sba[r * 32 + lane];
            hA[r * 32 + lane] = (v[r].x + bb) * gate[r].x;
            hB[r * 32 + lane] = (v[r].y + bb) * gate[r].y;
        }
    }
}

// Kernel 2: fc2 butterfly (1 stack, n=2048), keep first 1024 + bias -> out.
__global__ void __launch_bounds__(256, 1)
glu_k2(const float* __restrict__ tw2, const float* __restrict__ b2,
       float* __restrict__ out) {
    extern __shared__ float sm[];
    {
        const float4* s0 = (const float4*)tw2;
        float4* d = (float4*)sm;
        for (int i = threadIdx.x; i < TW2_FLOATS / 4; i += 256) d[i] = s0[i];
        float* sb = sm + TW2_FLOATS;
        for (int i = threadIdx.x; i < 1024; i += 256) sb[i] = b2[i];
    }
    __syncthreads();

    const float* sb = sm + TW2_FLOATS;
    const int lane = threadIdx.x & 31;
    const int warp = threadIdx.x >> 5;
    const int wglobal = blockIdx.x * 8 + warp;
    const int wstride = gridDim.x * 8;

    for (int rp = wglobal; rp < NROWS / 2; rp += wstride) {
        const float* hA = g_h + (size_t)(rp * 2) * N2;
        const float* hB = hA + N2;
        float2 v[64];
        #pragma unroll
        for (int r = 0; r < 64; r++) { v[r].x = hA[r * 32 + lane]; v[r].y = hB[r * 32 + lane]; }
        bfly<64, 11>(v, sm, lane);

        float* oA = out + (size_t)(rp * 2) * 1024;
        float* oB = oA + 1024;
        #pragma unroll
        for (int r = 0; r < 32; r++) {   // out_size = 1024: first 32 regs only
            float bb = sb[r * 32 + lane];
            oA[r * 32 + lane] = v[r].x + bb;
            oB[r * 32 + lane] = v[r].y + bb;
        }
    }
}

extern "C" void kernel_launch(void* const* d_in, const int* in_sizes, int n_in,
                              void* d_out, int out_size) {
    const float* x   = (const float*)d_in[0];
    const float* tw1 = (const float*)d_in[1];
    const float* b1  = (const float*)d_in[2];
    const float* tw2 = (const float*)d_in[3];
    const float* b2  = (const float*)d_in[4];
    float* out = (float*)d_out;

    const int smem1 = SMEM1_FLOATS * sizeof(float);   // 172032 B
    const int smem2 = SMEM2_FLOATS * sizeof(float);   // 184320 B
    cudaFuncSetAttribute(glu_k1, cudaFuncAttributeMaxDynamicSharedMemorySize, smem1);
    cudaFuncSetAttribute(glu_k2, cudaFuncAttributeMaxDynamicSharedMemorySize, smem2);

    glu_k1<<<152, 256, smem1>>>(x, tw1, b1);
    glu_k2<<<152, 256, smem2>>>(tw2, b2, out);
}

// round 3
// speedup vs baseline: 1.2405x; 1.2405x over previous
#include <cuda_runtime.h>
#include <cstdint>

#define NROWS   16384      // B*T = 4*4096
#define N1      1024
#define N2      2048
#define TW1_STACK_FLOATS (10*512*4)     // 20480 floats per stack (81920 B)
#define TW2_FLOATS       (11*1024*4)    // 45056 floats (180224 B)
#define SMEM1_BYTES ((TW1_STACK_FLOATS + 1024) * 4)   // 86016
#define SMEM2_BYTES ((TW2_FLOATS + 1024) * 4)         // 184320

// GLU intermediates: a+bias and sigmoid(gate+bias), each (NROWS, 2048) fp32 = 128MB
__device__ float g_a[(size_t)NROWS * N2];
__device__ float g_g[(size_t)NROWS * N2];

// ---------------- butterfly, 2 rows packed per float2 (k1) ----------------
template<int NREG, int NSTAGE>
__device__ __forceinline__ void bfly2(float2 (&v)[NREG], const float* __restrict__ tws, int lane) {
    constexpr int TSTAGE = NREG * 64;   // floats per stage = (NREG*32/2)*4
    // shuffle stages: stride 1..16 (partner differs in lane bits)
    #pragma unroll
    for (int idx = 0; idx < 5; idx++) {
        const int s = 1 << idx;
        const float* tstage = tws + idx * TSTAGE;
        const int i = (lane >> idx) & 1;
        #pragma unroll
        for (int r = 0; r < NREG; r++) {
            const int e = r * 32 + lane;
            const int p = ((e >> (idx + 1)) << idx) | (e & (s - 1));
            float2 t = *(const float2*)(tstage + p * 4 + i * 2);   // own row of 2x2
            float2 pv;
            pv.x = __shfl_xor_sync(0xffffffffu, v[r].x, s);
            pv.y = __shfl_xor_sync(0xffffffffu, v[r].y, s);
            float2 lo = i ? pv   : v[r];
            float2 hi = i ? v[r] : pv;
            v[r].x = fmaf(t.x, lo.x, t.y * hi.x);
            v[r].y = fmaf(t.x, lo.y, t.y * hi.y);
        }
    }
    // register-local stages: stride >= 32 (partner differs in reg index)
    #pragma unroll
    for (int idx = 5; idx < NSTAGE; idx++) {
        const int rs = 1 << (idx - 5);
        const float* tstage = tws + idx * TSTAGE;
        #pragma unroll
        for (int r = 0; r < NREG; r++) {
            if (r & rs) continue;
            const int r2 = r | rs;
            const int e = r * 32 + lane;
            const int p = ((e >> (idx + 1)) << idx) | (e & ((1 << idx) - 1));
            float4 t = *(const float4*)(tstage + p * 4);
            float2 lo = v[r], hi = v[r2];
            v[r].x  = fmaf(t.x, lo.x, t.y * hi.x);
            v[r].y  = fmaf(t.x, lo.y, t.y * hi.y);
            v[r2].x = fmaf(t.z, lo.x, t.w * hi.x);
            v[r2].y = fmaf(t.z, lo.y, t.w * hi.y);
        }
    }
}

// ---------------- butterfly, scalar 1 row (k2) ----------------
template<int NREG, int NSTAGE>
__device__ __forceinline__ void bfly1(float (&v)[NREG], const float* __restrict__ tws, int lane) {
    constexpr int TSTAGE = NREG * 64;
    #pragma unroll
    for (int idx = 0; idx < 5; idx++) {
        const int s = 1 << idx;
        const float* tstage = tws + idx * TSTAGE;
        const int i = (lane >> idx) & 1;
        #pragma unroll
        for (int r = 0; r < NREG; r++) {
            const int e = r * 32 + lane;
            const int p = ((e >> (idx + 1)) << idx) | (e & (s - 1));
            float2 t = *(const float2*)(tstage + p * 4 + i * 2);
            float pv = __shfl_xor_sync(0xffffffffu, v[r], s);
            float lo = i ? pv   : v[r];
            float hi = i ? v[r] : pv;
            v[r] = fmaf(t.x, lo, t.y * hi);
        }
    }
    #pragma unroll
    for (int idx = 5; idx < NSTAGE; idx++) {
        const int rs = 1 << (idx - 5);
        const float* tstage = tws + idx * TSTAGE;
        #pragma unroll
        for (int r = 0; r < NREG; r++) {
            if (r & rs) continue;
            const int r2 = r | rs;
            const int e = r * 32 + lane;
            const int p = ((e >> (idx + 1)) << idx) | (e & ((1 << idx) - 1));
            float4 t = *(const float4*)(tstage + p * 4);
            float lo = v[r], hi = v[r2];
            v[r]  = fmaf(t.x, lo, t.y * hi);
            v[r2] = fmaf(t.z, lo, t.w * hi);
        }
    }
}

// Kernel 1: fc1 butterfly, ONE stack per CTA (stack = blockIdx.x & 3).
// Stacks 0,1 -> g_a (a + bias); stacks 2,3 -> g_g (sigmoid(gate + bias)).
// 512 threads (16 warps), 2 rows per thread packed in float2.
__global__ void __launch_bounds__(512, 1)
glu_k1(const float* __restrict__ x, const float* __restrict__ tw1,
       const float* __restrict__ b1) {
    extern __shared__ float sm[];
    const int stack = blockIdx.x & 3;
    {
        const float4* src = (const float4*)(tw1 + stack * TW1_STACK_FLOATS);
        float4* d = (float4*)sm;
        for (int i = threadIdx.x; i < TW1_STACK_FLOATS / 4; i += 512) d[i] = src[i];
        float* sb = sm + TW1_STACK_FLOATS;
        for (int i = threadIdx.x; i < 1024; i += 512) sb[i] = b1[stack * 1024 + i];
    }
    __syncthreads();

    const float* sb = sm + TW1_STACK_FLOATS;
    const int lane = threadIdx.x & 31;
    const int warp = threadIdx.x >> 5;
    const int wglobal = (blockIdx.x >> 2) * 16 + warp;
    const int wstride = (gridDim.x >> 2) * 16;
    const bool isGate = (stack >= 2);
    float* dstBase = (isGate ? g_g : g_a) + (size_t)(stack & 1) * 1024;

    for (int rp = wglobal; rp < NROWS / 2; rp += wstride) {
        const float* xA = x + (size_t)(2 * rp) * N1;
        const float* xB = xA + N1;
        float2 v[32];
        #pragma unroll
        for (int r = 0; r < 32; r++) { v[r].x = xA[r * 32 + lane]; v[r].y = xB[r * 32 + lane]; }
        bfly2<32, 10>(v, sm, lane);

        float* oA = dstBase + (size_t)(2 * rp) * N2;
        float* oB = oA + N2;
        if (isGate) {
            #pragma unroll
            for (int r = 0; r < 32; r++) {
                float bb = sb[r * 32 + lane];
                oA[r * 32 + lane] = __fdividef(1.0f, 1.0f + __expf(-(v[r].x + bb)));
                oB[r * 32 + lane] = __fdividef(1.0f, 1.0f + __expf(-(v[r].y + bb)));
            }
        } else {
            #pragma unroll
            for (int r = 0; r < 32; r++) {
                float bb = sb[r * 32 + lane];
                oA[r * 32 + lane] = v[r].x + bb;
                oB[r * 32 + lane] = v[r].y + bb;
            }
        }
    }
}

// Kernel 2: GLU product fused at load (v = a * g), fc2 butterfly (n=2048),
// keep first 1024 + bias. 512 threads, 1 row per thread (64 data regs).
__global__ void __launch_bounds__(512, 1)
glu_k2(const float* __restrict__ tw2, const float* __restrict__ b2,
       float* __restrict__ out) {
    extern __shared__ float sm[];
    {
        const float4* src = (const float4*)tw2;
        float4* d = (float4*)sm;
        for (int i = threadIdx.x; i < TW2_FLOATS / 4; i += 512) d[i] = src[i];
        float* sb = sm + TW2_FLOATS;
        for (int i = threadIdx.x; i < 1024; i += 512) sb[i] = b2[i];
    }
    __syncthreads();

    const float* sb = sm + TW2_FLOATS;
    const int lane = threadIdx.x & 31;
    const int warp = threadIdx.x >> 5;
    const int wglobal = blockIdx.x * 16 + warp;
    const int wstride = gridDim.x * 16;

    for (int row = wglobal; row < NROWS; row += wstride) {
        const float* pa = g_a + (size_t)row * N2;
        const float* pg = g_g + (size_t)row * N2;
        float v[64];
        #pragma unroll
        for (int r = 0; r < 64; r++) v[r] = pa[r * 32 + lane] * pg[r * 32 + lane];
        bfly1<64, 11>(v, sm, lane);

        float* o = out + (size_t)row * 1024;
        #pragma unroll
        for (int r = 0; r < 32; r++)   // out_size = 1024: first 32 regs only
            o[r * 32 + lane] = v[r] + sb[r * 32 + lane];
    }
}

extern "C" void kernel_launch(void* const* d_in, const int* in_sizes, int n_in,
                              void* d_out, int out_size) {
    const float* x   = (const float*)d_in[0];
    const float* tw1 = (const float*)d_in[1];
    const float* b1  = (const float*)d_in[2];
    const float* tw2 = (const float*)d_in[3];
    const float* b2  = (const float*)d_in[4];
    float* out = (float*)d_out;

    cudaFuncSetAttribute(glu_k1, cudaFuncAttributeMaxDynamicSharedMemorySize, SMEM1_BYTES);
    cudaFuncSetAttribute(glu_k2, cudaFuncAttributeMaxDynamicSharedMemorySize, SMEM2_BYTES);

    glu_k1<<<148, 512, SMEM1_BYTES>>>(x, tw1, b1);   // 148 = 4 stacks * 37 row-blocks
    glu_k2<<<148, 512, SMEM2_BYTES>>>(tw2, b2, out);
}